// round 8
// baseline (speedup 1.0000x reference)
#include <cuda_runtime.h>
#include <cuda_fp16.h>
#include <cstdint>

#define BROWS 32768
#define HDIM  512

#define OFF_S2E 0
#define OFF_TF  1310720
#define OFF_FW  3932160
#define OFF_FG  6553600
#define OFF_WG  7864320
#define OFF_HD  9175040
#define WT_TOT  10223616

__device__ __half g_wh[WT_TOT];
__device__ __half g_wl[WT_TOT];
__device__ float g_e [BROWS*HDIM];
__device__ float g_f [BROWS*HDIM];
__device__ float g_w [BROWS*HDIM];
__device__ float g_fm[BROWS*HDIM];
__device__ float g_wm[BROWS*HDIM];
__device__ float g_h2[BROWS*HDIM];
__device__ float g_h3[BROWS*HDIM];

// ---------------- helpers ----------------
__device__ __forceinline__ uint32_t smem_u32(const void* p) {
    uint32_t a;
    asm("{ .reg .u64 t; cvta.to.shared.u64 t, %1; cvt.u32.u64 %0, t; }" : "=r"(a) : "l"(p));
    return a;
}
__device__ __forceinline__ void cpa16(uint32_t dst, const void* src) {
    asm volatile("cp.async.cg.shared.global [%0], [%1], 16;" :: "r"(dst), "l"(src));
}
#define CP_COMMIT() asm volatile("cp.async.commit_group;" ::: "memory")
#define CP_WAIT1()  asm volatile("cp.async.wait_group 1;" ::: "memory")
#define CP_WAIT0()  asm volatile("cp.async.wait_group 0;" ::: "memory")

#define LDM4(r, addr) \
    asm volatile("ldmatrix.sync.aligned.m8n8.x4.shared.b16 {%0,%1,%2,%3}, [%4];" \
        : "=r"((r)[0]), "=r"((r)[1]), "=r"((r)[2]), "=r"((r)[3]) : "r"(addr))

#define MMA(d, a, b) \
    asm volatile("mma.sync.aligned.m16n8k16.row.col.f32.f16.f16.f32 " \
        "{%0,%1,%2,%3}, {%4,%5,%6,%7}, {%8,%9}, {%0,%1,%2,%3};" \
        : "+f"((d)[0]), "+f"((d)[1]), "+f"((d)[2]), "+f"((d)[3]) \
        : "r"((a)[0]), "r"((a)[1]), "r"((a)[2]), "r"((a)[3]), "r"((b)[0]), "r"((b)[1]))

// transpose [K,512] fp32 -> [512,K] fp16 hi/lo (layer = blockIdx.z)
__global__ void prep_kernel(const float* src, __half* dh, __half* dl, int K) {
    __shared__ float tile[32][33];
    int z = blockIdx.z;
    src += (size_t)z * K * 512;
    size_t dof = (size_t)z * 512 * K;
    int k0 = blockIdx.x * 32, n0 = blockIdx.y * 32;
    int tx = threadIdx.x, ty = threadIdx.y;
    for (int r = ty; r < 32; r += 8)
        tile[r][tx] = src[(size_t)(k0 + r) * 512 + n0 + tx];
    __syncthreads();
    for (int r = ty; r < 32; r += 8) {
        float v = tile[tx][r];
        __half h = __float2half_rn(v);
        size_t o = dof + (size_t)(n0 + r) * K + k0 + tx;
        dh[o] = h;
        dl[o] = __float2half_rn(v - __half2float(h));
    }
}

// smem: fp16 tiles, 144-byte padded rows (K=64 -> 128B data + 16B pad)
#define AH0 0
#define AH1 18432
#define BH0 36864
#define BL0 55296
#define BH1 73728
#define BL1 92160
#define SMEM_SZ 110592

// modes: 0 bias  1 bias+add  2 gelu(x+bias)  3 add + sigmoid(x+bias)*(mix-add)
__global__ void __launch_bounds__(256, 2) gemm_kernel(
    const float* A1, const float* A2,
    const __half* Bh, const __half* Bl, int Ktot,
    const float* bias, int mode, const float* add, const float* mix, float* out)
{
    extern __shared__ char smem[];
    const uint32_t sb = smem_u32(smem);
    const int tid = threadIdx.x, lane = tid & 31, wid = tid >> 5;
    const int m0 = blockIdx.y * 128, n0 = blockIdx.x * 128;
    const int wm = wid & 1, wn = wid >> 1;        // warp tile: 64M x 32N
    const int rowT = tid >> 1, segT = tid & 1;    // copy lanes: row 0..127, seg 0..1

    float acc[4][4][4];
    #pragma unroll
    for (int i = 0; i < 4; i++)
        #pragma unroll
        for (int j = 0; j < 4; j++)
            #pragma unroll
            for (int q = 0; q < 4; q++) acc[i][j][q] = 0.f;

    const int NC = Ktot >> 6;
    uint32_t aR[16];   // this thread's A row-half, packed half2 (32 fp16)

#define LDGA(cc) do {                                                              \
    int kg_ = (cc) * 64;                                                           \
    const float* Ap_ = (kg_ < 512) ? A1 : A2;                                      \
    int kk_ = (kg_ < 512) ? kg_ : kg_ - 512;                                       \
    const float4* s_ = (const float4*)(Ap_ + (size_t)(m0 + rowT) * HDIM + kk_ + segT * 32); \
    _Pragma("unroll")                                                              \
    for (int q = 0; q < 8; q++) {                                                  \
        float4 v = s_[q];                                                          \
        __half2 p0 = __floats2half2_rn(v.x, v.y);                                  \
        __half2 p1 = __floats2half2_rn(v.z, v.w);                                  \
        aR[2 * q]     = *(uint32_t*)&p0;                                           \
        aR[2 * q + 1] = *(uint32_t*)&p1;                                           \
    }                                                                              \
} while (0)

#define ISSUEB(cc, buf) do {                                                       \
    int kg_ = (cc) * 64;                                                           \
    size_t bo_ = (size_t)(n0 + rowT) * Ktot + kg_ + segT * 32;                     \
    uint32_t bd_ = sb + ((buf) ? BH1 : BH0) + rowT * 144 + segT * 64;              \
    const __half* ph_ = Bh + bo_;                                                  \
    cpa16(bd_, ph_); cpa16(bd_ + 16, ph_ + 8);                                     \
    cpa16(bd_ + 32, ph_ + 16); cpa16(bd_ + 48, ph_ + 24);                          \
    uint32_t ld_ = sb + ((buf) ? BL1 : BL0) + rowT * 144 + segT * 64;              \
    const __half* pl_ = Bl + bo_;                                                  \
    cpa16(ld_, pl_); cpa16(ld_ + 16, pl_ + 8);                                     \
    cpa16(ld_ + 32, pl_ + 16); cpa16(ld_ + 48, pl_ + 24);                          \
    CP_COMMIT();                                                                   \
} while (0)

    LDGA(0);
    ISSUEB(0, 0);

    // ldmatrix lane addressing (same fragment scheme as validated R7 kernel)
    const int arow  = wm * 64 + (lane & 15);
    const int acolb = ((lane >> 4) & 1) * 16;
    const int g = lane >> 3, lr = lane & 7;
    const int brow  = wn * 32 + ((g & 2) ? 8 : 0) + lr;
    const int bcolb = (g & 1) * 16;

    for (int c = 0; c < NC; c++) {
        __syncthreads();   // all ldmatrix reads of buffers (c-2, c-1) complete
        // publish A(c) from regs into fp16 smem tile
        {
            char* ab = smem + ((c & 1) ? AH1 : AH0) + rowT * 144 + segT * 64;
            uint4* av = (uint4*)aR;
            ((uint4*)ab)[0] = av[0]; ((uint4*)ab)[1] = av[1];
            ((uint4*)ab)[2] = av[2]; ((uint4*)ab)[3] = av[3];
        }
        if (c + 1 < NC) { LDGA(c + 1); ISSUEB(c + 1, (c + 1) & 1); CP_WAIT1(); }
        else            { CP_WAIT0(); }
        __syncthreads();   // A(c) + B(c) visible to all

        const uint32_t ahb = sb + ((c & 1) ? AH1 : AH0);
        const uint32_t bhb = sb + ((c & 1) ? BH1 : BH0);
        const uint32_t blb = sb + ((c & 1) ? BL1 : BL0);
        #pragma unroll
        for (int ks = 0; ks < 4; ks++) {
            uint32_t af[4][4];
            #pragma unroll
            for (int i = 0; i < 4; i++)
                LDM4(af[i], ahb + (uint32_t)((arow + i * 16) * 144 + ks * 32 + acolb));
            #pragma unroll
            for (int jp = 0; jp < 2; jp++) {
                uint32_t bo = (uint32_t)((brow + jp * 16) * 144 + ks * 32 + bcolb);
                uint32_t bh_[4], bl_[4];
                LDM4(bh_, bhb + bo);
                LDM4(bl_, blb + bo);
                #pragma unroll
                for (int i = 0; i < 4; i++) {
                    #pragma unroll
                    for (int jj = 0; jj < 2; jj++) {
                        float* d = acc[i][jp * 2 + jj];
                        MMA(d, af[i], bh_ + 2 * jj);
                        MMA(d, af[i], bl_ + 2 * jj);
                    }
                }
            }
        }
    }

    // epilogue: fused bias / residual / gelu / sigmoid-gate, float2 stores
    const int r0b = m0 + wm * 64 + (lane >> 2);
    const int cb  = n0 + wn * 32 + (lane & 3) * 2;
    const float is2 = 0.7071067811865475f;
    #pragma unroll
    for (int i = 0; i < 4; i++) {
        #pragma unroll
        for (int j = 0; j < 4; j++) {
            int cc = cb + j * 8;
            float b0 = bias[cc], b1 = bias[cc + 1];
            #pragma unroll
            for (int h = 0; h < 2; h++) {
                int rr = r0b + i * 16 + h * 8;
                size_t gix = (size_t)rr * HDIM + cc;
                float v0 = acc[i][j][h * 2 + 0] + b0;
                float v1 = acc[i][j][h * 2 + 1] + b1;
                float2 res;
                if (mode == 0) {
                    res.x = v0; res.y = v1;
                } else if (mode == 1) {
                    float2 ad = *(const float2*)(add + gix);
                    res.x = v0 + ad.x; res.y = v1 + ad.y;
                } else if (mode == 2) {
                    res.x = 0.5f * v0 * (1.f + erff(v0 * is2));
                    res.y = 0.5f * v1 * (1.f + erff(v1 * is2));
                } else {
                    float2 ad = *(const float2*)(add + gix);
                    float2 mx = *(const float2*)(mix + gix);
                    float s0 = 1.f / (1.f + __expf(-v0));
                    float s1 = 1.f / (1.f + __expf(-v1));
                    res.x = ad.x + s0 * (mx.x - ad.x);
                    res.y = ad.y + s1 * (mx.y - ad.y);
                }
                *(float2*)(out + gix) = res;
            }
        }
    }
}

// tiny second-layer heads: out[B,7]
__global__ void heads_kernel(
    const float* hs, const float* he, const float* hf, const float* hw,
    const float* Ws, const float* bs, const float* We, const float* be,
    const float* Wf, const float* bfv, const float* Ww, const float* bw,
    float* out)
{
    int gw = (int)((blockIdx.x * blockDim.x + threadIdx.x) >> 5);
    int lane = threadIdx.x & 31;
    if (gw >= BROWS) return;
    size_t base = (size_t)gw * HDIM;
    float a[7] = {0, 0, 0, 0, 0, 0, 0};
    #pragma unroll
    for (int t = 0; t < 16; t++) {
        int k = t * 32 + lane;
        float vs = hs[base + k], ve = he[base + k], vf = hf[base + k], vw = hw[base + k];
        a[0] += vs * Ws[k * 3 + 0]; a[1] += vs * Ws[k * 3 + 1]; a[2] += vs * Ws[k * 3 + 2];
        a[3] += ve * We[k];
        a[4] += vf * Wf[k];
        a[5] += vw * Ww[k * 2 + 0]; a[6] += vw * Ww[k * 2 + 1];
    }
    #pragma unroll
    for (int j = 0; j < 7; j++)
        #pragma unroll
        for (int s = 16; s > 0; s >>= 1)
            a[j] += __shfl_xor_sync(~0u, a[j], s);
    if (lane == 0) {
        float* o = out + (size_t)gw * 7;
        o[0] = a[0] + bs[0]; o[1] = a[1] + bs[1]; o[2] = a[2] + bs[2];
        o[3] = a[3] + be[0];
        o[4] = a[4] + bfv[0];
        o[5] = a[5] + bw[0]; o[6] = a[6] + bw[1];
    }
}

static void gemm(const float* A1, const float* A2, const __half* Bh,
                 const __half* Bl, int K, const float* bias, int mode,
                 const float* add, const float* mix, float* out) {
    gemm_kernel<<<dim3(4, 256), 256, SMEM_SZ>>>(A1, A2, Bh, Bl, K, bias, mode, add, mix, out);
}

extern "C" void kernel_launch(void* const* d_in, const int* in_sizes, int n_in,
                              void* d_out, int out_size) {
    const float* sh = (const float*)d_in[0];
    cudaFuncSetAttribute(gemm_kernel, cudaFuncAttributeMaxDynamicSharedMemorySize, SMEM_SZ);

    __half *wh, *wl;
    float *e, *f, *w, *fm, *wm, *h2, *h3;
    cudaGetSymbolAddress((void**)&wh, g_wh);
    cudaGetSymbolAddress((void**)&wl, g_wl);
    cudaGetSymbolAddress((void**)&e,  g_e);
    cudaGetSymbolAddress((void**)&f,  g_f);
    cudaGetSymbolAddress((void**)&w,  g_w);
    cudaGetSymbolAddress((void**)&fm, g_fm);
    cudaGetSymbolAddress((void**)&wm, g_wm);
    cudaGetSymbolAddress((void**)&h2, g_h2);
    cudaGetSymbolAddress((void**)&h3, g_h3);

    const size_t SB = (size_t)BROWS * HDIM * sizeof(float);
    cudaMemcpyAsync(e, d_in[1], SB, cudaMemcpyDeviceToDevice);
    cudaMemcpyAsync(f, d_in[2], SB, cudaMemcpyDeviceToDevice);
    cudaMemcpyAsync(w, d_in[3], SB, cudaMemcpyDeviceToDevice);

    dim3 tb(32, 8);
    prep_kernel<<<dim3(16, 16, 5), tb>>>((const float*)d_in[4],  wh + OFF_S2E, wl + OFF_S2E, 512);
    prep_kernel<<<dim3(32, 16, 5), tb>>>((const float*)d_in[6],  wh + OFF_TF,  wl + OFF_TF, 1024);
    prep_kernel<<<dim3(32, 16, 5), tb>>>((const float*)d_in[8],  wh + OFF_FW,  wl + OFF_FW, 1024);
    prep_kernel<<<dim3(16, 16, 5), tb>>>((const float*)d_in[10], wh + OFF_FG,  wl + OFF_FG, 512);
    prep_kernel<<<dim3(16, 16, 5), tb>>>((const float*)d_in[12], wh + OFF_WG,  wl + OFF_WG, 512);
    for (int j = 0; j < 4; j++)
        prep_kernel<<<dim3(16, 16, 1), tb>>>((const float*)d_in[14 + 4 * j],
                                             wh + OFF_HD + j * 262144, wl + OFF_HD + j * 262144, 512);

    for (int i = 0; i < 5; i++) {
        const float* s2e_b = (const float*)d_in[5]  + i * 512;
        const float* tf_b  = (const float*)d_in[7]  + i * 512;
        const float* fw_b  = (const float*)d_in[9]  + i * 512;
        const float* fg_b  = (const float*)d_in[11] + i * 512;
        const float* wg_b  = (const float*)d_in[13] + i * 512;
        int o1 = i * 262144, o2 = i * 524288;
        gemm(sh, nullptr, wh + OFF_S2E + o1, wl + OFF_S2E + o1, 512, s2e_b, 1, e, nullptr, e);
        gemm(sh, e, wh + OFF_TF + o2, wl + OFF_TF + o2, 1024, tf_b, 0, nullptr, nullptr, fm);
        gemm(fm, nullptr, wh + OFF_FG + o1, wl + OFF_FG + o1, 512, fg_b, 3, f, fm, f);
        gemm(e, f, wh + OFF_FW + o2, wl + OFF_FW + o2, 1024, fw_b, 0, nullptr, nullptr, wm);
        gemm(wm, nullptr, wh + OFF_WG + o1, wl + OFF_WG + o1, 512, wg_b, 3, w, wm, w);
    }
    gemm(sh, nullptr, wh + OFF_HD + 0 * 262144, wl + OFF_HD + 0 * 262144, 512,
         (const float*)d_in[15], 2, nullptr, nullptr, fm);
    gemm(e, nullptr, wh + OFF_HD + 1 * 262144, wl + OFF_HD + 1 * 262144, 512,
         (const float*)d_in[19], 2, nullptr, nullptr, wm);
    gemm(f, nullptr, wh + OFF_HD + 2 * 262144, wl + OFF_HD + 2 * 262144, 512,
         (const float*)d_in[23], 2, nullptr, nullptr, h2);
    gemm(w, nullptr, wh + OFF_HD + 3 * 262144, wl + OFF_HD + 3 * 262144, 512,
         (const float*)d_in[27], 2, nullptr, nullptr, h3);

    heads_kernel<<<BROWS / 8, 256>>>(
        fm, wm, h2, h3,
        (const float*)d_in[16], (const float*)d_in[17],
        (const float*)d_in[20], (const float*)d_in[21],
        (const float*)d_in[24], (const float*)d_in[25],
        (const float*)d_in[28], (const float*)d_in[29],
        (float*)d_out);
}

// round 9
// speedup vs baseline: 1.7674x; 1.7674x over previous
#include <cuda_runtime.h>
#include <cuda_fp16.h>
#include <cstdint>

#define BROWS 32768
#define HDIM  512

#define OFF_S2E 0
#define OFF_TF  1310720
#define OFF_FW  3932160
#define OFF_FG  6553600
#define OFF_WG  7864320
#define OFF_HD  9175040
#define WT_TOT  10223616

__device__ __half g_wh[WT_TOT];
__device__ __half g_wl[WT_TOT];
__device__ float g_e [BROWS*HDIM];
__device__ float g_f [BROWS*HDIM];
__device__ float g_w [BROWS*HDIM];
__device__ float g_fm[BROWS*HDIM];
__device__ float g_wm[BROWS*HDIM];
__device__ float g_h2[BROWS*HDIM];
__device__ float g_h3[BROWS*HDIM];

// ---------------- helpers ----------------
__device__ __forceinline__ uint32_t smem_u32(const void* p) {
    uint32_t a;
    asm("{ .reg .u64 t; cvta.to.shared.u64 t, %1; cvt.u32.u64 %0, t; }" : "=r"(a) : "l"(p));
    return a;
}
__device__ __forceinline__ void cpa16(uint32_t dst, const void* src) {
    asm volatile("cp.async.cg.shared.global [%0], [%1], 16;" :: "r"(dst), "l"(src));
}
#define CP_COMMIT() asm volatile("cp.async.commit_group;" ::: "memory")
#define CP_WAIT1()  asm volatile("cp.async.wait_group 1;" ::: "memory")
#define CP_WAIT0()  asm volatile("cp.async.wait_group 0;" ::: "memory")

#define LDM4(r, addr) \
    asm volatile("ldmatrix.sync.aligned.m8n8.x4.shared.b16 {%0,%1,%2,%3}, [%4];" \
        : "=r"((r)[0]), "=r"((r)[1]), "=r"((r)[2]), "=r"((r)[3]) : "r"(addr))

#define MMA(d, a, b) \
    asm volatile("mma.sync.aligned.m16n8k16.row.col.f32.f16.f16.f32 " \
        "{%0,%1,%2,%3}, {%4,%5,%6,%7}, {%8,%9}, {%0,%1,%2,%3};" \
        : "+f"((d)[0]), "+f"((d)[1]), "+f"((d)[2]), "+f"((d)[3]) \
        : "r"((a)[0]), "r"((a)[1]), "r"((a)[2]), "r"((a)[3]), "r"((b)[0]), "r"((b)[1]))

// transpose [K,512] fp32 -> [512,K] fp16 hi/lo (layer = blockIdx.z)
__global__ void prep_kernel(const float* src, __half* dh, __half* dl, int K) {
    __shared__ float tile[32][33];
    int z = blockIdx.z;
    src += (size_t)z * K * 512;
    size_t dof = (size_t)z * 512 * K;
    int k0 = blockIdx.x * 32, n0 = blockIdx.y * 32;
    int tx = threadIdx.x, ty = threadIdx.y;
    for (int r = ty; r < 32; r += 8)
        tile[r][tx] = src[(size_t)(k0 + r) * 512 + n0 + tx];
    __syncthreads();
    for (int r = ty; r < 32; r += 8) {
        float v = tile[tx][r];
        __half h = __float2half_rn(v);
        size_t o = dof + (size_t)(n0 + r) * K + k0 + tx;
        dh[o] = h;
        dl[o] = __float2half_rn(v - __half2float(h));
    }
}

// smem byte offsets (dynamic smem)
#define AF0 0
#define AF1 18432
#define AHO 36864
#define BH0 47104
#define BL0 57344
#define BH1 67584
#define BL1 77824
#define SMEM_SZ 88064

// modes: 0 bias  1 bias+add  2 gelu(x+bias)  3 add + sigmoid(x+bias)*(mix-add)
__global__ void __launch_bounds__(256, 2) gemm_kernel(
    const float* A1, const float* A2,
    const __half* Bh, const __half* Bl, int Ktot,
    const float* bias, int mode, const float* add, const float* mix, float* out)
{
    extern __shared__ char smem[];
    const uint32_t sb = smem_u32(smem);
    const int tid = threadIdx.x, lane = tid & 31, wid = tid >> 5;
    const int m0 = blockIdx.y * 128, n0 = blockIdx.x * 128;
    const int wm = wid & 3, wn = wid >> 2;
    const int rowA = tid >> 1, segA = tid & 1;

    float acc[2][8][4];
    #pragma unroll
    for (int i = 0; i < 2; i++)
        #pragma unroll
        for (int j = 0; j < 8; j++)
            #pragma unroll
            for (int q = 0; q < 4; q++) acc[i][j][q] = 0.f;

    const int NC = Ktot >> 5;

#define ISSUE(cc, buf) do {                                                        \
    int kg_ = (cc) * 32;                                                           \
    const float* Ap_ = (kg_ < 512) ? A1 : A2;                                      \
    int kk_ = (kg_ < 512) ? kg_ : kg_ - 512;                                       \
    const float* as_ = Ap_ + (size_t)(m0 + rowA) * HDIM + kk_ + segA * 16;         \
    uint32_t ad_ = sb + ((buf) ? AF1 : AF0) + rowA * 144 + segA * 64;              \
    cpa16(ad_, as_); cpa16(ad_ + 16, as_ + 4);                                     \
    cpa16(ad_ + 32, as_ + 8); cpa16(ad_ + 48, as_ + 12);                           \
    size_t bo_ = (size_t)(n0 + rowA) * Ktot + kg_ + segA * 16;                     \
    uint32_t bd_ = sb + ((buf) ? BH1 : BH0) + rowA * 80 + segA * 32;               \
    cpa16(bd_, Bh + bo_); cpa16(bd_ + 16, Bh + bo_ + 8);                           \
    uint32_t ld_ = sb + ((buf) ? BL1 : BL0) + rowA * 80 + segA * 32;               \
    cpa16(ld_, Bl + bo_); cpa16(ld_ + 16, Bl + bo_ + 8);                           \
    CP_COMMIT();                                                                   \
} while (0)

    ISSUE(0, 0);

    // ldmatrix lane addressing
    const int arow = wm * 32 + (lane & 15);
    const int acolb = ((lane >> 4) & 1) * 16;           // byte offset (k half)
    const int g = lane >> 3, lr = lane & 7;
    const int brow = wn * 64 + ((g & 2) ? 8 : 0) + lr;  // n row within tile
    const int bcolb = (g & 1) * 16;

    for (int c = 0; c < NC; c++) {
        __syncthreads();                 // previous compute done on all threads
        if (c + 1 < NC) { ISSUE(c + 1, (c + 1) & 1); CP_WAIT1(); }
        else            { CP_WAIT0(); }

        // convert this thread's own copied A rows: fp32 -> fp16 (hi only)
        {
            const float* af = (const float*)(smem + ((c & 1) ? AF1 : AF0)) + rowA * 36 + segA * 16;
            float4 q0 = *(const float4*)(af + 0);
            float4 q1 = *(const float4*)(af + 4);
            float4 q2 = *(const float4*)(af + 8);
            float4 q3 = *(const float4*)(af + 12);
            uint4 H0, H1;
            __half2 t;
            t = __floats2half2_rn(q0.x, q0.y); H0.x = *(uint32_t*)&t;
            t = __floats2half2_rn(q0.z, q0.w); H0.y = *(uint32_t*)&t;
            t = __floats2half2_rn(q1.x, q1.y); H0.z = *(uint32_t*)&t;
            t = __floats2half2_rn(q1.z, q1.w); H0.w = *(uint32_t*)&t;
            t = __floats2half2_rn(q2.x, q2.y); H1.x = *(uint32_t*)&t;
            t = __floats2half2_rn(q2.z, q2.w); H1.y = *(uint32_t*)&t;
            t = __floats2half2_rn(q3.x, q3.y); H1.z = *(uint32_t*)&t;
            t = __floats2half2_rn(q3.z, q3.w); H1.w = *(uint32_t*)&t;
            char* ah = smem + AHO + rowA * 80 + segA * 32;
            *(uint4*)(ah) = H0; *(uint4*)(ah + 16) = H1;
        }
        __syncthreads();                 // A converted, B(c) visible everywhere

        const uint32_t bhb = sb + ((c & 1) ? BH1 : BH0);
        const uint32_t blb = sb + ((c & 1) ? BL1 : BL0);
        #pragma unroll
        for (int ks = 0; ks < 2; ks++) {
            uint32_t ah_[2][4];
            #pragma unroll
            for (int i = 0; i < 2; i++) {
                uint32_t ao = (uint32_t)((arow + i * 16) * 80 + ks * 32 + acolb);
                LDM4(ah_[i], sb + AHO + ao);
            }
            #pragma unroll
            for (int jp = 0; jp < 4; jp++) {
                uint32_t bo = (uint32_t)((brow + jp * 16) * 80 + ks * 32 + bcolb);
                uint32_t bh_[4], bl_[4];
                LDM4(bh_, bhb + bo);
                LDM4(bl_, blb + bo);
                #pragma unroll
                for (int i = 0; i < 2; i++) {
                    #pragma unroll
                    for (int jj = 0; jj < 2; jj++) {
                        float* d = acc[i][jp * 2 + jj];
                        MMA(d, ah_[i], bh_ + 2 * jj);
                        MMA(d, ah_[i], bl_ + 2 * jj);
                    }
                }
            }
        }
    }

    // epilogue: thread owns (rows r0,r0+8) x col pairs, float2 stores
    const int r0b = m0 + wm * 32 + (lane >> 2);
    const int cb  = n0 + wn * 64 + (lane & 3) * 2;
    const float is2 = 0.7071067811865475f;
    #pragma unroll
    for (int i = 0; i < 2; i++) {
        #pragma unroll
        for (int j = 0; j < 8; j++) {
            int cc = cb + j * 8;
            float b0 = bias[cc], b1 = bias[cc + 1];
            #pragma unroll
            for (int h = 0; h < 2; h++) {
                int rr = r0b + i * 16 + h * 8;
                size_t gix = (size_t)rr * HDIM + cc;
                float v0 = acc[i][j][h * 2 + 0] + b0;
                float v1 = acc[i][j][h * 2 + 1] + b1;
                float2 res;
                if (mode == 0) {
                    res.x = v0; res.y = v1;
                } else if (mode == 1) {
                    float2 ad = *(const float2*)(add + gix);
                    res.x = v0 + ad.x; res.y = v1 + ad.y;
                } else if (mode == 2) {
                    res.x = 0.5f * v0 * (1.f + erff(v0 * is2));
                    res.y = 0.5f * v1 * (1.f + erff(v1 * is2));
                } else {
                    float2 ad = *(const float2*)(add + gix);
                    float2 mx = *(const float2*)(mix + gix);
                    float s0 = 1.f / (1.f + __expf(-v0));
                    float s1 = 1.f / (1.f + __expf(-v1));
                    res.x = ad.x + s0 * (mx.x - ad.x);
                    res.y = ad.y + s1 * (mx.y - ad.y);
                }
                *(float2*)(out + gix) = res;
            }
        }
    }
}

// tiny second-layer heads: out[B,7]
__global__ void heads_kernel(
    const float* hs, const float* he, const float* hf, const float* hw,
    const float* Ws, const float* bs, const float* We, const float* be,
    const float* Wf, const float* bfv, const float* Ww, const float* bw,
    float* out)
{
    int gw = (int)((blockIdx.x * blockDim.x + threadIdx.x) >> 5);
    int lane = threadIdx.x & 31;
    if (gw >= BROWS) return;
    size_t base = (size_t)gw * HDIM;
    float a[7] = {0, 0, 0, 0, 0, 0, 0};
    #pragma unroll
    for (int t = 0; t < 16; t++) {
        int k = t * 32 + lane;
        float vs = hs[base + k], ve = he[base + k], vf = hf[base + k], vw = hw[base + k];
        a[0] += vs * Ws[k * 3 + 0]; a[1] += vs * Ws[k * 3 + 1]; a[2] += vs * Ws[k * 3 + 2];
        a[3] += ve * We[k];
        a[4] += vf * Wf[k];
        a[5] += vw * Ww[k * 2 + 0]; a[6] += vw * Ww[k * 2 + 1];
    }
    #pragma unroll
    for (int j = 0; j < 7; j++)
        #pragma unroll
        for (int s = 16; s > 0; s >>= 1)
            a[j] += __shfl_xor_sync(~0u, a[j], s);
    if (lane == 0) {
        float* o = out + (size_t)gw * 7;
        o[0] = a[0] + bs[0]; o[1] = a[1] + bs[1]; o[2] = a[2] + bs[2];
        o[3] = a[3] + be[0];
        o[4] = a[4] + bfv[0];
        o[5] = a[5] + bw[0]; o[6] = a[6] + bw[1];
    }
}

static void gemm(const float* A1, const float* A2, const __half* Bh,
                 const __half* Bl, int K, const float* bias, int mode,
                 const float* add, const float* mix, float* out) {
    gemm_kernel<<<dim3(4, 256), 256, SMEM_SZ>>>(A1, A2, Bh, Bl, K, bias, mode, add, mix, out);
}

extern "C" void kernel_launch(void* const* d_in, const int* in_sizes, int n_in,
                              void* d_out, int out_size) {
    const float* sh = (const float*)d_in[0];
    cudaFuncSetAttribute(gemm_kernel, cudaFuncAttributeMaxDynamicSharedMemorySize, SMEM_SZ);

    __half *wh, *wl;
    float *e, *f, *w, *fm, *wm, *h2, *h3;
    cudaGetSymbolAddress((void**)&wh, g_wh);
    cudaGetSymbolAddress((void**)&wl, g_wl);
    cudaGetSymbolAddress((void**)&e,  g_e);
    cudaGetSymbolAddress((void**)&f,  g_f);
    cudaGetSymbolAddress((void**)&w,  g_w);
    cudaGetSymbolAddress((void**)&fm, g_fm);
    cudaGetSymbolAddress((void**)&wm, g_wm);
    cudaGetSymbolAddress((void**)&h2, g_h2);
    cudaGetSymbolAddress((void**)&h3, g_h3);

    const size_t SB = (size_t)BROWS * HDIM * sizeof(float);
    cudaMemcpyAsync(e, d_in[1], SB, cudaMemcpyDeviceToDevice);
    cudaMemcpyAsync(f, d_in[2], SB, cudaMemcpyDeviceToDevice);
    cudaMemcpyAsync(w, d_in[3], SB, cudaMemcpyDeviceToDevice);

    dim3 tb(32, 8);
    prep_kernel<<<dim3(16, 16, 5), tb>>>((const float*)d_in[4],  wh + OFF_S2E, wl + OFF_S2E, 512);
    prep_kernel<<<dim3(32, 16, 5), tb>>>((const float*)d_in[6],  wh + OFF_TF,  wl + OFF_TF, 1024);
    prep_kernel<<<dim3(32, 16, 5), tb>>>((const float*)d_in[8],  wh + OFF_FW,  wl + OFF_FW, 1024);
    prep_kernel<<<dim3(16, 16, 5), tb>>>((const float*)d_in[10], wh + OFF_FG,  wl + OFF_FG, 512);
    prep_kernel<<<dim3(16, 16, 5), tb>>>((const float*)d_in[12], wh + OFF_WG,  wl + OFF_WG, 512);
    for (int j = 0; j < 4; j++)
        prep_kernel<<<dim3(16, 16, 1), tb>>>((const float*)d_in[14 + 4 * j],
                                             wh + OFF_HD + j * 262144, wl + OFF_HD + j * 262144, 512);

    for (int i = 0; i < 5; i++) {
        const float* s2e_b = (const float*)d_in[5]  + i * 512;
        const float* tf_b  = (const float*)d_in[7]  + i * 512;
        const float* fw_b  = (const float*)d_in[9]  + i * 512;
        const float* fg_b  = (const float*)d_in[11] + i * 512;
        const float* wg_b  = (const float*)d_in[13] + i * 512;
        int o1 = i * 262144, o2 = i * 524288;
        gemm(sh, nullptr, wh + OFF_S2E + o1, wl + OFF_S2E + o1, 512, s2e_b, 1, e, nullptr, e);
        gemm(sh, e, wh + OFF_TF + o2, wl + OFF_TF + o2, 1024, tf_b, 0, nullptr, nullptr, fm);
        gemm(fm, nullptr, wh + OFF_FG + o1, wl + OFF_FG + o1, 512, fg_b, 3, f, fm, f);
        gemm(e, f, wh + OFF_FW + o2, wl + OFF_FW + o2, 1024, fw_b, 0, nullptr, nullptr, wm);
        gemm(wm, nullptr, wh + OFF_WG + o1, wl + OFF_WG + o1, 512, wg_b, 3, w, wm, w);
    }
    gemm(sh, nullptr, wh + OFF_HD + 0 * 262144, wl + OFF_HD + 0 * 262144, 512,
         (const float*)d_in[15], 2, nullptr, nullptr, fm);
    gemm(e, nullptr, wh + OFF_HD + 1 * 262144, wl + OFF_HD + 1 * 262144, 512,
         (const float*)d_in[19], 2, nullptr, nullptr, wm);
    gemm(f, nullptr, wh + OFF_HD + 2 * 262144, wl + OFF_HD + 2 * 262144, 512,
         (const float*)d_in[23], 2, nullptr, nullptr, h2);
    gemm(w, nullptr, wh + OFF_HD + 3 * 262144, wl + OFF_HD + 3 * 262144, 512,
         (const float*)d_in[27], 2, nullptr, nullptr, h3);

    heads_kernel<<<BROWS / 8, 256>>>(
        fm, wm, h2, h3,
        (const float*)d_in[16], (const float*)d_in[17],
        (const float*)d_in[20], (const float*)d_in[21],
        (const float*)d_in[24], (const float*)d_in[25],
        (const float*)d_in[28], (const float*)d_in[29],
        (float*)d_out);
}